// round 4
// baseline (speedup 1.0000x reference)
#include <cuda_runtime.h>
#include <cstdint>

#define BATCH        32768
#define FEAT_DIM     512
#define NUM_CLASSES  1000
#define KC           2
#define WARPS_PER_BLOCK 8
#define THREADS   (WARPS_PER_BLOCK * 32)

// Scratch via __device__ globals (allocation-free).
__device__ double        g_acc;
__device__ int           g_is64;
__device__ unsigned int  g_count;

// Detect label dtype (int32 vs int64) + zero accumulators.
// 512 threads read the 512 odd 32-bit words of the first 4 KB (in-bounds for
// either dtype: buffer is >= 128 KB). int64 little-endian small labels have
// all-zero high words; int32 random labels in [0,1000) cannot.
__global__ __launch_bounds__(512) void mcl_prep(const int* __restrict__ labels_words) {
    const int v = labels_words[2 * threadIdx.x + 1];
    const int any_nz = __syncthreads_or(v != 0);
    if (threadIdx.x == 0) {
        g_is64 = any_nz ? 0 : 1;
        g_acc = 0.0;
        g_count = 0u;
    }
}

// min-blocks=3 -> register budget ~84/thread: lets ptxas keep all 12 float4
// loads (48 data regs) in flight per lane instead of serializing at 32 regs.
__global__ __launch_bounds__(THREADS, 3) void mcl_main(
    const float* __restrict__ x,
    const void*  __restrict__ labels,
    const float* __restrict__ centers,
    float*       __restrict__ out)
{
    // Grid exactly covers BATCH warps (4096 blocks * 8 warps) -> no bounds check.
    const int warp_global = (blockIdx.x * THREADS + threadIdx.x) >> 5;
    const int lane = threadIdx.x & 31;
    const int warp_local = threadIdx.x >> 5;

    const float4* __restrict__ xr = reinterpret_cast<const float4*>(
        x + (size_t)warp_global * FEAT_DIM);

    // x loads are label-independent: issue them first so they overlap the
    // label -> center-pointer dependency chain.
    float4 xv[4];
    #pragma unroll
    for (int i = 0; i < 4; i++) xv[i] = xr[lane + 32 * i];

    long long lbl;
    if (g_is64)
        lbl = ((const long long*)labels)[warp_global];
    else
        lbl = (long long)((const int*)labels)[warp_global];
    if (lbl < 0 || lbl >= NUM_CLASSES) lbl = 0;   // defensive clamp

    const float4* __restrict__ c0 = reinterpret_cast<const float4*>(
        centers + (size_t)lbl * (KC * FEAT_DIM));
    const float4* __restrict__ c1 = c0 + (FEAT_DIM / 4);

    float4 av[4], bv[4];
    #pragma unroll
    for (int i = 0; i < 4; i++) av[i] = c0[lane + 32 * i];
    #pragma unroll
    for (int i = 0; i < 4; i++) bv[i] = c1[lane + 32 * i];

    float d0 = 0.0f, d1 = 0.0f;
    #pragma unroll
    for (int i = 0; i < 4; i++) {
        float t;
        t = xv[i].x - av[i].x; d0 = fmaf(t, t, d0);
        t = xv[i].y - av[i].y; d0 = fmaf(t, t, d0);
        t = xv[i].z - av[i].z; d0 = fmaf(t, t, d0);
        t = xv[i].w - av[i].w; d0 = fmaf(t, t, d0);
        t = xv[i].x - bv[i].x; d1 = fmaf(t, t, d1);
        t = xv[i].y - bv[i].y; d1 = fmaf(t, t, d1);
        t = xv[i].z - bv[i].z; d1 = fmaf(t, t, d1);
        t = xv[i].w - bv[i].w; d1 = fmaf(t, t, d1);
    }

    // Warp tree-reduce both sums, then min over the K=2 centers.
    #pragma unroll
    for (int off = 16; off > 0; off >>= 1) {
        d0 += __shfl_xor_sync(0xffffffffu, d0, off);
        d1 += __shfl_xor_sync(0xffffffffu, d1, off);
    }
    float md = fminf(d0, d1);

    __shared__ float s_part[WARPS_PER_BLOCK];
    if (lane == 0) s_part[warp_local] = md;
    __syncthreads();

    if (threadIdx.x == 0) {
        float block_sum = 0.0f;
        #pragma unroll
        for (int i = 0; i < WARPS_PER_BLOCK; i++) block_sum += s_part[i];
        atomicAdd(&g_acc, (double)block_sum);
        __threadfence();
        unsigned int done = atomicAdd(&g_count, 1u);
        if (done == gridDim.x - 1) {
            out[0] = (float)(g_acc / (double)BATCH);
        }
    }
}

extern "C" void kernel_launch(void* const* d_in, const int* in_sizes, int n_in,
                              void* d_out, int out_size)
{
    // Identify inputs by element count (robust to ordering):
    //   x: 32768*512 = 16777216, centers: 2000*512 = 1024000, labels: 32768.
    const float* x       = nullptr;
    const void*  labels  = nullptr;
    const float* centers = nullptr;
    for (int i = 0; i < n_in; i++) {
        if (in_sizes[i] == BATCH * FEAT_DIM)                 x = (const float*)d_in[i];
        else if (in_sizes[i] == NUM_CLASSES * KC * FEAT_DIM) centers = (const float*)d_in[i];
        else if (in_sizes[i] == BATCH)                       labels = d_in[i];
    }
    float* out = (float*)d_out;

    mcl_prep<<<1, 512>>>((const int*)labels);

    const int blocks = BATCH / WARPS_PER_BLOCK;   // 4096
    mcl_main<<<blocks, THREADS>>>(x, labels, centers, out);
}

// round 5
// speedup vs baseline: 1.1951x; 1.1951x over previous
#include <cuda_runtime.h>
#include <cstdint>

#define BATCH        32768
#define FEAT_DIM     512
#define NUM_CLASSES  1000
#define KC           2
#define WARPS_PER_BLOCK 8
#define THREADS   (WARPS_PER_BLOCK * 32)
#define SAMPLES_PER_WARP 4
#define BLOCKS    (BATCH / (WARPS_PER_BLOCK * SAMPLES_PER_WARP))   // 1024

// Scratch via __device__ globals (allocation-free).
__device__ double        g_acc;
__device__ int           g_is64;
__device__ unsigned int  g_count;

// Detect label dtype (int32 vs int64) + zero accumulators.
// 512 threads read the 512 odd 32-bit words of the first 4 KB (in-bounds for
// either dtype: buffer is >= 128 KB). int64 little-endian small labels have
// all-zero high words; int32 random labels in [0,1000) cannot.
__global__ __launch_bounds__(512) void mcl_prep(const int* __restrict__ labels_words) {
    const int v = labels_words[2 * threadIdx.x + 1];
    const int any_nz = __syncthreads_or(v != 0);
    if (threadIdx.x == 0) {
        g_is64 = any_nz ? 0 : 1;
        g_acc = 0.0;
        g_count = 0u;
    }
}

// min-blocks=5 -> ~51 regs/thread, 40 warps/SM (62% occ): middle ground that
// lets ptxas pipeline across the 4 independent per-sample chains.
__global__ __launch_bounds__(THREADS, 5) void mcl_main(
    const float* __restrict__ x,
    const void*  __restrict__ labels,
    const float* __restrict__ centers,
    float*       __restrict__ out)
{
    const int lane = threadIdx.x & 31;
    const int warp_local = threadIdx.x >> 5;
    const int warp_id = blockIdx.x * WARPS_PER_BLOCK + warp_local;  // 0..8191
    const int base_sample = warp_id * SAMPLES_PER_WARP;

    // Prefetch all 4 labels in one coalesced access: lanes 0-3 each load one,
    // then broadcast via shfl. Pays the label latency ONCE per warp.
    long long my_lbl = 0;
    if (lane < SAMPLES_PER_WARP) {
        if (g_is64)
            my_lbl = ((const long long*)labels)[base_sample + lane];
        else
            my_lbl = (long long)((const int*)labels)[base_sample + lane];
    }

    float sum_min = 0.0f;   // sum over this warp's samples of min-distance (lane-partial)

    #pragma unroll
    for (int s = 0; s < SAMPLES_PER_WARP; s++) {
        // x loads for sample s are label-independent; ptxas can hoist them
        // ahead of / across the label broadcast and prior samples' FMAs.
        const float4* __restrict__ xr = reinterpret_cast<const float4*>(
            x + (size_t)(base_sample + s) * FEAT_DIM);

        long long lbl = __shfl_sync(0xffffffffu, my_lbl, s);
        if (lbl < 0 || lbl >= NUM_CLASSES) lbl = 0;   // defensive clamp

        const float4* __restrict__ c0 = reinterpret_cast<const float4*>(
            centers + (size_t)lbl * (KC * FEAT_DIM));
        const float4* __restrict__ c1 = c0 + (FEAT_DIM / 4);

        float d0 = 0.0f, d1 = 0.0f;
        #pragma unroll
        for (int i = 0; i < FEAT_DIM / 4 / 32; i++) {   // 4 chunks of float4
            const int idx = lane + 32 * i;
            const float4 xv = xr[idx];
            const float4 a  = c0[idx];
            const float4 b  = c1[idx];
            float t;
            t = xv.x - a.x; d0 = fmaf(t, t, d0);
            t = xv.y - a.y; d0 = fmaf(t, t, d0);
            t = xv.z - a.z; d0 = fmaf(t, t, d0);
            t = xv.w - a.w; d0 = fmaf(t, t, d0);
            t = xv.x - b.x; d1 = fmaf(t, t, d1);
            t = xv.y - b.y; d1 = fmaf(t, t, d1);
            t = xv.z - b.z; d1 = fmaf(t, t, d1);
            t = xv.w - b.w; d1 = fmaf(t, t, d1);
        }

        // Warp tree-reduce both sums, min over the K=2 centers, accumulate.
        #pragma unroll
        for (int off = 16; off > 0; off >>= 1) {
            d0 += __shfl_xor_sync(0xffffffffu, d0, off);
            d1 += __shfl_xor_sync(0xffffffffu, d1, off);
        }
        sum_min += fminf(d0, d1);   // identical value on all lanes
    }

    __shared__ float s_part[WARPS_PER_BLOCK];
    if (lane == 0) s_part[warp_local] = sum_min;
    __syncthreads();

    if (threadIdx.x == 0) {
        float block_sum = 0.0f;
        #pragma unroll
        for (int i = 0; i < WARPS_PER_BLOCK; i++) block_sum += s_part[i];
        atomicAdd(&g_acc, (double)block_sum);
        __threadfence();
        unsigned int done = atomicAdd(&g_count, 1u);
        if (done == gridDim.x - 1) {
            out[0] = (float)(g_acc / (double)BATCH);
        }
    }
}

extern "C" void kernel_launch(void* const* d_in, const int* in_sizes, int n_in,
                              void* d_out, int out_size)
{
    // Identify inputs by element count (robust to ordering):
    //   x: 32768*512 = 16777216, centers: 2000*512 = 1024000, labels: 32768.
    const float* x       = nullptr;
    const void*  labels  = nullptr;
    const float* centers = nullptr;
    for (int i = 0; i < n_in; i++) {
        if (in_sizes[i] == BATCH * FEAT_DIM)                 x = (const float*)d_in[i];
        else if (in_sizes[i] == NUM_CLASSES * KC * FEAT_DIM) centers = (const float*)d_in[i];
        else if (in_sizes[i] == BATCH)                       labels = d_in[i];
    }
    float* out = (float*)d_out;

    mcl_prep<<<1, 512>>>((const int*)labels);
    mcl_main<<<BLOCKS, THREADS>>>(x, labels, centers, out);
}